// round 12
// baseline (speedup 1.0000x reference)
#include <cuda_runtime.h>
#include <cstdint>

// Row gather via fully-async path: out[row][:] = table[idx[row]][:].
// NEW mechanism (only class untried in R4-R11): no register landing.
//   1. per-lane coalesced index load + shfl distribution (as before)
//   2. cp.async (LDGSTS, 16B) gathers table rows global->smem, fire-and-forget
//   3. one cp.async.bulk (UBLKCP) per block stores 32KB contiguous smem->gmem
// Removes the per-warp L2-latency scoreboard stall on gather data and all
// per-thread STGs.

static constexpr int  EMB_DIM        = 32;
static constexpr long NROWS          = 4096L * 26L * 2L;   // 212992
static constexpr int  THREADS        = 256;
static constexpr int  ROWS_PER_WARP  = 32;
static constexpr int  WARPS_PER_BLOCK= THREADS / 32;       // 8
static constexpr int  ROWS_PER_BLOCK = WARPS_PER_BLOCK * ROWS_PER_WARP;  // 256
static constexpr int  BLOCKS         = (int)(NROWS / ROWS_PER_BLOCK);    // 832, exact
static constexpr int  STEPS          = 8;                   // 4 rows per step
static constexpr int  ROW_BYTES      = EMB_DIM * 4;         // 128
static constexpr int  TILE_BYTES     = ROWS_PER_BLOCK * ROW_BYTES;  // 32768

__global__ __launch_bounds__(THREADS)
void gather_rows_kernel(const void*  __restrict__ idx_raw,
                        const float* __restrict__ table,
                        float*       __restrict__ out)
{
    __shared__ __align__(128) char tile[TILE_BYTES];

    const int lane = threadIdx.x & 31;
    const int warp = threadIdx.x >> 5;

    // ---- per-warp dtype probe: high words of first 32 8-byte pairs ----
    unsigned int hiw = ((const unsigned int*)idx_raw)[2 * lane + 1];
    const bool is32 = __any_sync(0xffffffffu, hiw != 0);

    const long rowBase = ((long)blockIdx.x * WARPS_PER_BLOCK + warp) * ROWS_PER_WARP;

    // ---- one coalesced index load: lane L carries row rowBase+L ----
    long long myIdx;
    if (is32) myIdx = (long long)__ldg(((const int*)idx_raw) + rowBase + lane);
    else      myIdx = __ldg(((const long long*)idx_raw) + rowBase + lane);

    const int subrow = lane >> 3;   // 0..3: row within a 4-row step
    const int col    = lane & 7;    // 16B chunk within the 128B row

    long r[STEPS];
#pragma unroll
    for (int s = 0; s < STEPS; s++)
        r[s] = (long)__shfl_sync(0xffffffffu, myIdx, s * 4 + subrow);

    // ---- 8 fire-and-forget 16B async gathers per thread (no reg landing) ----
    unsigned int smem_base;
    asm("{ .reg .u64 t; cvta.to.shared.u64 t, %1; cvt.u32.u64 %0, t; }"
        : "=r"(smem_base) : "l"(tile));

#pragma unroll
    for (int s = 0; s < STEPS; s++) {
        const float* src = table + r[s] * EMB_DIM + col * 4;
        unsigned int dst = smem_base
                         + ((warp * ROWS_PER_WARP + s * 4 + subrow) * 8 + col) * 16;
        asm volatile("cp.async.ca.shared.global [%0], [%1], 16;"
                     :: "r"(dst), "l"(src) : "memory");
    }
    asm volatile("cp.async.commit_group;" ::: "memory");
    asm volatile("cp.async.wait_group 0;" ::: "memory");
    __syncthreads();

    // ---- one 32KB contiguous bulk store per block ----
    if (threadIdx.x == 0) {
        asm volatile("fence.proxy.async.shared::cta;" ::: "memory");
        float* dst = out + (long)blockIdx.x * ROWS_PER_BLOCK * EMB_DIM;
        asm volatile("cp.async.bulk.global.shared::cta.bulk_group [%0], [%1], %2;"
                     :: "l"(dst), "r"(smem_base), "r"((unsigned)TILE_BYTES)
                     : "memory");
        asm volatile("cp.async.bulk.commit_group;" ::: "memory");
        // smem is freed at CTA exit: must drain before returning.
        asm volatile("cp.async.bulk.wait_group 0;" ::: "memory");
    }
}

extern "C" void kernel_launch(void* const* d_in, const int* in_sizes, int n_in,
                              void* d_out, int out_size)
{
    // Pick the index tensor by element count (212992 vs 32,000,000).
    const void*  idx;
    const float* table;
    if (in_sizes[0] == (int)NROWS) {
        idx   = d_in[0];
        table = (const float*)d_in[1];
    } else {
        idx   = d_in[1];
        table = (const float*)d_in[0];
    }

    gather_rows_kernel<<<BLOCKS, THREADS>>>(idx, table, (float*)d_out);
}